// round 1
// baseline (speedup 1.0000x reference)
#include <cuda_runtime.h>
#include <cuda_bf16.h>

// Problem constants (fixed by the reference):
//   x: (B=8, C=64, H=512, W=512) fp32
//   groupn: (G=16, N=4) fp32
//   out[b,g,h,w] = sum_n x[b, IDX[g,n], h, w] * groupn[g,n]
//   IDX[g,n] = (g/4)*16 + n*4 + (g%4)
//
// Pure HBM-bound weighted channel reduction. Vectorize with float4,
// one thread per output float4, 4 coalesced input streams per (b,g).

static constexpr int B = 8;
static constexpr int C = 64;
static constexpr int G = 16;
static constexpr int HW = 512 * 512;          // elements per plane
static constexpr int HW4 = HW / 4;            // float4s per plane = 65536

__global__ __launch_bounds__(256)
void binnings_kernel(const float4* __restrict__ x,
                     const float* __restrict__ groupn,
                     float4* __restrict__ out)
{
    const int g = blockIdx.y;      // 0..15
    const int b = blockIdx.z;      // 0..7
    const int p = blockIdx.x * blockDim.x + threadIdx.x;   // float4 index within plane

    // Gathered channels for this group: base, base+4, base+8, base+12
    const int ch_base = (g >> 2) * 16 + (g & 3);

    // Uniform per-block weight loads (L1/const-cached)
    const float w0 = __ldg(&groupn[g * 4 + 0]);
    const float w1 = __ldg(&groupn[g * 4 + 1]);
    const float w2 = __ldg(&groupn[g * 4 + 2]);
    const float w3 = __ldg(&groupn[g * 4 + 3]);

    // float4-unit plane offsets
    const long long base = (long long)(b * C + ch_base) * HW4 + p;

    const float4 a0 = __ldg(&x[base + 0LL * 4 * HW4]);
    const float4 a1 = __ldg(&x[base + 1LL * 4 * HW4]);
    const float4 a2 = __ldg(&x[base + 2LL * 4 * HW4]);
    const float4 a3 = __ldg(&x[base + 3LL * 4 * HW4]);

    float4 r;
    r.x = fmaf(a0.x, w0, fmaf(a1.x, w1, fmaf(a2.x, w2, a3.x * w3)));
    r.y = fmaf(a0.y, w0, fmaf(a1.y, w1, fmaf(a2.y, w2, a3.y * w3)));
    r.z = fmaf(a0.z, w0, fmaf(a1.z, w1, fmaf(a2.z, w2, a3.z * w3)));
    r.w = fmaf(a0.w, w0, fmaf(a1.w, w1, fmaf(a2.w, w2, a3.w * w3)));

    out[(long long)(b * G + g) * HW4 + p] = r;
}

extern "C" void kernel_launch(void* const* d_in, const int* in_sizes, int n_in,
                              void* d_out, int out_size)
{
    const float4* x      = (const float4*)d_in[0];
    const float*  groupn = (const float*)d_in[1];
    float4*       out    = (float4*)d_out;

    dim3 block(256);
    dim3 grid(HW4 / 256, G, B);   // 256 x 16 x 8 blocks
    binnings_kernel<<<grid, block>>>(x, groupn, out);
}